// round 12
// baseline (speedup 1.0000x reference)
#include <cuda_runtime.h>
#include <math.h>

#define EPS 1e-5f
#define TS 8
#define HALO 14          // TS + 6
#define PSTR 68          // per-pixel channel stride in floats (64 + 4 pad)
#define NHALO 196        // 14*14
#define TSTR 20          // ts row stride (16 + 4 pad, float4-aligned)

// smem layout (floats)
#define OFF_XS   0
#define OFF_TS   (OFF_XS   + NHALO * PSTR)     // 13328
#define OFF_X1S  (OFF_TS   + 64 * TSTR)        // +1280
#define OFF_INVP (OFF_X1S  + 64 * PSTR)        // +4352
#define OFF_WRS  (OFF_INVP + 64 * PSTR)        // +4352
#define OFF_WSPT (OFF_WRS  + 1024)
#define OFF_BSPS (OFF_WSPT + 4 * 16 * 52)      // +3328
#define OFF_WCS  (OFF_BSPS + 4 * 52)           // +208
#define OFF_WMS  (OFF_WCS  + 128 * PSTR)       // +8704
#define OFF_BVS  (OFF_WMS  + 128 * PSTR)       // +8704
#define SMEM_FLOATS (OFF_BVS + 128)
#define SMEM_BYTES (SMEM_FLOATS * 4)

__device__ __forceinline__ float dot4acc(float4 w, float4 v, float a) {
    a = fmaf(w.x, v.x, a);
    a = fmaf(w.y, v.y, a);
    a = fmaf(w.z, v.z, a);
    a = fmaf(w.w, v.w, a);
    return a;
}

__device__ __forceinline__ float gelu_exact(float v) {
    return 0.5f * v * (1.0f + erff(v * 0.70710678118654752f));
}

// Partial involution over kernel taps [KB, KB+NKK).
template<int KB, int NKK>
__device__ __forceinline__ void inv_partial(
    const float* __restrict__ wspT, const float* __restrict__ bsps,
    const float* __restrict__ ts, const float4* __restrict__ xs4,
    int p, int q, int py, int px, float* inv)
{
    constexpr int NK4 = (NKK + 3) / 4;
    float kern[NK4 * 4];

    // bias slice (padded to 52, over-read harmless)
    const float4* b4 = (const float4*)bsps + q * 13 + KB / 4;
    #pragma unroll
    for (int j = 0; j < NK4; j++) {
        float4 b = b4[j];
        kern[j * 4 + 0] = b.x; kern[j * 4 + 1] = b.y;
        kern[j * 4 + 2] = b.z; kern[j * 4 + 3] = b.w;
    }

    // span GEMM slice: kern[kk] += sum_r wspT[q][r][kk] * t[r]
    const float4* t4 = (const float4*)(ts + p * TSTR);
    #pragma unroll
    for (int r4 = 0; r4 < 4; r4++) {
        float4 tv = t4[r4];
        float tvals[4] = {tv.x, tv.y, tv.z, tv.w};
        #pragma unroll
        for (int rj = 0; rj < 4; rj++) {
            int r = r4 * 4 + rj;
            const float4* w4 = (const float4*)(wspT + (q * 16 + r) * 52) + KB / 4;
            float t_ = tvals[rj];
            #pragma unroll
            for (int j = 0; j < NK4; j++) {
                float4 w = w4[j];
                kern[j * 4 + 0] = fmaf(w.x, t_, kern[j * 4 + 0]);
                kern[j * 4 + 1] = fmaf(w.y, t_, kern[j * 4 + 1]);
                kern[j * 4 + 2] = fmaf(w.z, t_, kern[j * 4 + 2]);
                kern[j * 4 + 3] = fmaf(w.w, t_, kern[j * 4 + 3]);
            }
        }
    }

    // involution over this tap range, all 16 channels of group q
    #pragma unroll
    for (int j = 0; j < NKK; j++) {
        int kk = KB + j;
        int ki = kk / 7, kj = kk % 7;
        float kv = kern[j];
        const float4* xp = xs4 + ((py + ki) * HALO + (px + kj)) * (PSTR / 4) + q * 4;
        float4 v0 = xp[0], v1 = xp[1], v2 = xp[2], v3 = xp[3];
        inv[0]  = fmaf(kv, v0.x, inv[0]);
        inv[1]  = fmaf(kv, v0.y, inv[1]);
        inv[2]  = fmaf(kv, v0.z, inv[2]);
        inv[3]  = fmaf(kv, v0.w, inv[3]);
        inv[4]  = fmaf(kv, v1.x, inv[4]);
        inv[5]  = fmaf(kv, v1.y, inv[5]);
        inv[6]  = fmaf(kv, v1.z, inv[6]);
        inv[7]  = fmaf(kv, v1.w, inv[7]);
        inv[8]  = fmaf(kv, v2.x, inv[8]);
        inv[9]  = fmaf(kv, v2.y, inv[9]);
        inv[10] = fmaf(kv, v2.z, inv[10]);
        inv[11] = fmaf(kv, v2.w, inv[11]);
        inv[12] = fmaf(kv, v3.x, inv[12]);
        inv[13] = fmaf(kv, v3.y, inv[13]);
        inv[14] = fmaf(kv, v3.z, inv[14]);
        inv[15] = fmaf(kv, v3.w, inv[15]);
    }
}

__global__ __launch_bounds__(512, 1)
void fused_bottleneck(
    const float* __restrict__ x,
    const float* __restrict__ w_reduce,
    const float* __restrict__ g_r, const float* __restrict__ b_r,
    const float* __restrict__ m_r, const float* __restrict__ v_r,
    const float* __restrict__ w_span, const float* __restrict__ b_span,
    const float* __restrict__ g_i, const float* __restrict__ b_i,
    const float* __restrict__ m_i, const float* __restrict__ v_i,
    const float* __restrict__ w_conv,
    const float* __restrict__ g_c, const float* __restrict__ b_c,
    const float* __restrict__ m_c, const float* __restrict__ v_c,
    const float* __restrict__ w_map, const float* __restrict__ b_map,
    const float* __restrict__ g_m, const float* __restrict__ b_m,
    const float* __restrict__ m_m, const float* __restrict__ v_m,
    float* __restrict__ out)
{
    extern __shared__ float sm[];
    float* xs   = sm + OFF_XS;    // [196][68] halo tile
    float* ts   = sm + OFF_TS;    // [64][20]  reduced features
    float* x1s  = sm + OFF_X1S;   // [64][68]  gelu(bn(inv))
    float* invP = sm + OFF_INVP;  // [64][68]  h=1 partial involution
    float* wrs  = sm + OFF_WRS;   // [16][64]
    float* wspT = sm + OFF_WSPT;  // [4][16][52] span weights, transposed+padded
    float* bsps = sm + OFF_BSPS;  // [4][52]   span bias, padded
    float* wcs  = sm + OFF_WCS;   // [128][68] bn-folded w_conv
    float* wms  = sm + OFF_WMS;   // [128][68] bn-folded w_map
    float* bvs  = sm + OFF_BVS;   // [128]     fused bias

    const int tid = threadIdx.x;
    const int gx0 = blockIdx.x * TS;
    const int gy0 = blockIdx.y * TS;
    const int bb  = blockIdx.z;
    const float* xb = x + (size_t)bb * 64 * 96 * 96;

    // ---- Stage halo (zero-padded) ----
    for (int i = tid; i < NHALO * 64; i += 512) {
        int c = i / NHALO;
        int p = i - c * NHALO;
        int hy = p / HALO;
        int hx = p - hy * HALO;
        int gy = gy0 + hy - 3;
        int gx = gx0 + hx - 3;
        float v = 0.0f;
        if ((unsigned)gy < 96u && (unsigned)gx < 96u)
            v = xb[(c * 96 + gy) * 96 + gx];
        xs[p * PSTR + c] = v;
    }
    // ---- Stage weights ----
    for (int i = tid; i < 1024; i += 512) wrs[i] = w_reduce[i];
    for (int i = tid; i < 4 * 16 * 52; i += 512) {
        int q = i / 832;
        int rem = i - q * 832;
        int r = rem / 52;
        int kk = rem - r * 52;
        wspT[i] = (kk < 49) ? w_span[(q * 49 + kk) * 16 + r] : 0.0f;
    }
    for (int i = tid; i < 4 * 52; i += 512) {
        int q = i / 52, kk = i - q * 52;
        bsps[i] = (kk < 49) ? b_span[q * 49 + kk] : 0.0f;
    }
    for (int i = tid; i < 8192; i += 512) {
        int o = i >> 6, c = i & 63;
        float scc = g_c[o] * rsqrtf(v_c[o] + EPS);
        float scm = g_m[o] * rsqrtf(v_m[o] + EPS);
        wcs[o * PSTR + c] = w_conv[i] * scc;
        wms[o * PSTR + c] = w_map[i]  * scm;
    }
    if (tid < 128) {
        float scc = g_c[tid] * rsqrtf(v_c[tid] + EPS);
        float scm = g_m[tid] * rsqrtf(v_m[tid] + EPS);
        bvs[tid] = (b_c[tid] - m_c[tid] * scc)
                 + scm * b_map[tid]
                 + (b_m[tid] - m_m[tid] * scm);
    }
    __syncthreads();

    const int p  = tid & 63;           // pixel in 8x8 tile
    const int py = p >> 3, px = p & 7;
    const int q  = (tid >> 6) & 3;     // involution group (warp-uniform)
    const int h  = tid >> 8;           // tap-range half (warp-uniform)
    const int cpix = (py + 3) * HALO + (px + 3);
    const float4* xs4 = (const float4*)xs;

    // ---- Phase 1: t = relu(bn(w_reduce @ x_center)), 2 rows per thread ----
    {
        const int rr = tid >> 6;       // 0..7 -> rows rr*2, rr*2+1
        float a0 = 0.f, a1 = 0.f;
        const float4* xc4 = xs4 + cpix * (PSTR / 4);
        const float4* wr4 = (const float4*)wrs;
        #pragma unroll
        for (int c4 = 0; c4 < 16; c4++) {
            float4 xv = xc4[c4];
            a0 = dot4acc(wr4[(rr * 2 + 0) * 16 + c4], xv, a0);
            a1 = dot4acc(wr4[(rr * 2 + 1) * 16 + c4], xv, a1);
        }
        float accv[2] = {a0, a1};
        #pragma unroll
        for (int j = 0; j < 2; j++) {
            int r = rr * 2 + j;
            float s = g_r[r] * rsqrtf(v_r[r] + EPS);
            float tv = fmaf(accv[j], s, b_r[r] - m_r[r] * s);
            ts[p * TSTR + r] = fmaxf(tv, 0.0f);
        }
    }
    __syncthreads();

    // ---- Phases 2+3: balanced partial span GEMM + partial involution ----
    float inv[16];
    #pragma unroll
    for (int j = 0; j < 16; j++) inv[j] = 0.0f;
    if (h == 0)
        inv_partial<0, 24>(wspT, bsps, ts, xs4, p, q, py, px, inv);
    else
        inv_partial<24, 25>(wspT, bsps, ts, xs4, p, q, py, px, inv);

    // h=1 publishes its partial; h=0 combines
    if (h == 1) {
        float4* dst = (float4*)(invP + p * PSTR + q * 16);
        #pragma unroll
        for (int j4 = 0; j4 < 4; j4++)
            dst[j4] = make_float4(inv[j4*4+0], inv[j4*4+1], inv[j4*4+2], inv[j4*4+3]);
    }
    __syncthreads();

    // ---- Phase 4: x1 = gelu(bn_i(inv)) -> smem (h=0 threads) ----
    if (h == 0) {
        const float4* src = (const float4*)(invP + p * PSTR + q * 16);
        float4* dst = (float4*)(x1s + p * PSTR + q * 16);
        #pragma unroll
        for (int j4 = 0; j4 < 4; j4++) {
            float4 pr = src[j4];
            float prv[4] = {pr.x, pr.y, pr.z, pr.w};
            float vv[4];
            #pragma unroll
            for (int k = 0; k < 4; k++) {
                int c = q * 16 + j4 * 4 + k;
                float s = g_i[c] * rsqrtf(v_i[c] + EPS);
                float v = fmaf(inv[j4 * 4 + k] + prv[k], s, b_i[c] - m_i[c] * s);
                vv[k] = gelu_exact(v);
            }
            dst[j4] = make_float4(vv[0], vv[1], vv[2], vv[3]);
        }
    }
    __syncthreads();

    // ---- Phase 5: out = gelu(wcs@x1 + wms@x + bias) ----
    // 8 outputs x 2 strided pixels per thread; og warp-uniform so ALL weight
    // loads are single-address broadcasts (1 wf each). Input lane stride is
    // 1 pixel (68 words) -> conflict-free LDS.128.
    const int og = tid >> 5;   // 0..15 -> outputs og*8..og*8+7 (warp-uniform)
    const int pg = tid & 31;   // pixels {pg, pg+32}
    const int o0 = og * 8;

    float acc[8][2];
    #pragma unroll
    for (int j = 0; j < 8; j++) {
        float bv = bvs[o0 + j];
        acc[j][0] = bv;
        acc[j][1] = bv;
    }
    int x1o[2], xco[2];
    #pragma unroll
    for (int i = 0; i < 2; i++) {
        int pix = pg + 32 * i;
        int py2 = pix >> 3, px2 = pix & 7;
        x1o[i] = pix * (PSTR / 4);
        xco[i] = ((py2 + 3) * HALO + (px2 + 3)) * (PSTR / 4);
    }
    const float4* x14 = (const float4*)x1s;
    const float4* wcB = (const float4*)(wcs + o0 * PSTR);
    const float4* wmB = (const float4*)(wms + o0 * PSTR);

    #pragma unroll 2
    for (int c4 = 0; c4 < 16; c4++) {
        float4 xv1a = x14[x1o[0] + c4];
        float4 xv1b = x14[x1o[1] + c4];
        float4 xv0a = xs4[xco[0] + c4];
        float4 xv0b = xs4[xco[1] + c4];
        #pragma unroll
        for (int j = 0; j < 8; j++) {
            float4 wc = wcB[j * (PSTR / 4) + c4];
            float4 wm = wmB[j * (PSTR / 4) + c4];
            acc[j][0] = dot4acc(wc, xv1a, acc[j][0]);
            acc[j][0] = dot4acc(wm, xv0a, acc[j][0]);
            acc[j][1] = dot4acc(wc, xv1b, acc[j][1]);
            acc[j][1] = dot4acc(wm, xv0b, acc[j][1]);
        }
    }

    // ---- Store (final gelu) ----
    float* ob = out + (size_t)bb * 128 * 96 * 96;
    const int row0 = gy0 + (pg >> 3);
    const int colp = gx0 + (pg & 7);
    #pragma unroll
    for (int j = 0; j < 8; j++) {
        int o = o0 + j;
        ob[(o * 96 + row0)     * 96 + colp] = gelu_exact(acc[j][0]);
        ob[(o * 96 + row0 + 4) * 96 + colp] = gelu_exact(acc[j][1]);
    }
}

extern "C" void kernel_launch(void* const* d_in, const int* in_sizes, int n_in,
                              void* d_out, int out_size) {
    const float* x        = (const float*)d_in[0];
    const float* w_reduce = (const float*)d_in[1];
    const float* g_r      = (const float*)d_in[2];
    const float* b_r      = (const float*)d_in[3];
    const float* m_r      = (const float*)d_in[4];
    const float* v_r      = (const float*)d_in[5];
    const float* w_span   = (const float*)d_in[6];
    const float* b_span   = (const float*)d_in[7];
    const float* g_i      = (const float*)d_in[8];
    const float* b_i      = (const float*)d_in[9];
    const float* m_i      = (const float*)d_in[10];
    const float* v_i      = (const float*)d_in[11];
    const float* w_conv   = (const float*)d_in[12];
    const float* g_c      = (const float*)d_in[13];
    const float* b_c      = (const float*)d_in[14];
    const float* m_c      = (const float*)d_in[15];
    const float* v_c      = (const float*)d_in[16];
    const float* w_map    = (const float*)d_in[17];
    const float* b_map    = (const float*)d_in[18];
    const float* g_m      = (const float*)d_in[19];
    const float* b_m      = (const float*)d_in[20];
    const float* m_m      = (const float*)d_in[21];
    const float* v_m      = (const float*)d_in[22];

    cudaFuncSetAttribute(fused_bottleneck,
                         cudaFuncAttributeMaxDynamicSharedMemorySize, SMEM_BYTES);

    dim3 grid(96 / TS, 96 / TS, 4);
    dim3 block(512);
    fused_bottleneck<<<grid, block, SMEM_BYTES>>>(
        x, w_reduce, g_r, b_r, m_r, v_r, w_span, b_span,
        g_i, b_i, m_i, v_i, w_conv, g_c, b_c, m_c, v_c,
        w_map, b_map, g_m, b_m, m_m, v_m, (float*)d_out);
}

// round 14
// speedup vs baseline: 1.0932x; 1.0932x over previous
#include <cuda_runtime.h>
#include <math.h>

#define EPS 1e-5f
#define TS 8
#define HALO 14          // TS + 6
#define PSTR 68          // per-pixel channel stride in floats (64 + 4 pad)
#define NHALO 196        // 14*14
#define TSTR 20          // ts row stride

// smem layout (floats) — total 28000 floats = 112,000 B  (fits 2 CTAs/SM)
#define OFF_XS   0
#define OFF_TS   (OFF_XS   + NHALO * PSTR)     // 13328
#define OFF_X1S  (OFF_TS   + 64 * TSTR)        // +1280
#define OFF_WRS  (OFF_X1S  + 64 * PSTR)        // +4352
#define OFF_WSPT (OFF_WRS  + 1024)
#define OFF_BSPS (OFF_WSPT + 3328)
#define OFF_BVS  (OFF_BSPS + 208)
#define OFF_WBUF (OFF_BVS  + 128)              // [2][32][68] rotating weights
#define SMEM_FLOATS (OFF_WBUF + 2 * 32 * PSTR) // +4352
#define SMEM_BYTES (SMEM_FLOATS * 4)

// Pre-folded weights (written by fold_weights kernel each launch)
__device__ float g_wcF[8192];    // w_conv * bn_c scale, [o][c]
__device__ float g_wmF[8192];    // w_map  * bn_m scale, [o][c]
__device__ float g_bvF[128];     // fused bias
__device__ float g_wspTF[3328];  // span weights transposed [q][r][52]
__device__ float g_bspsF[208];   // span bias padded [q][52]

__device__ __forceinline__ float dot4acc(float4 w, float4 v, float a) {
    a = fmaf(w.x, v.x, a);
    a = fmaf(w.y, v.y, a);
    a = fmaf(w.z, v.z, a);
    a = fmaf(w.w, v.w, a);
    return a;
}

__device__ __forceinline__ float gelu_exact(float v) {
    return 0.5f * v * (1.0f + erff(v * 0.70710678118654752f));
}

__global__ void fold_weights(
    const float* __restrict__ w_span, const float* __restrict__ b_span,
    const float* __restrict__ w_conv,
    const float* __restrict__ g_c, const float* __restrict__ b_c,
    const float* __restrict__ m_c, const float* __restrict__ v_c,
    const float* __restrict__ w_map, const float* __restrict__ b_map,
    const float* __restrict__ g_m, const float* __restrict__ b_m,
    const float* __restrict__ m_m, const float* __restrict__ v_m)
{
    int i = blockIdx.x * 256 + threadIdx.x;
    if (i < 8192) {
        int o = i >> 6;
        float scc = g_c[o] * rsqrtf(v_c[o] + EPS);
        float scm = g_m[o] * rsqrtf(v_m[o] + EPS);
        g_wcF[i] = w_conv[i] * scc;
        g_wmF[i] = w_map[i]  * scm;
    }
    if (i < 128) {
        float scc = g_c[i] * rsqrtf(v_c[i] + EPS);
        float scm = g_m[i] * rsqrtf(v_m[i] + EPS);
        g_bvF[i] = (b_c[i] - m_c[i] * scc)
                 + scm * b_map[i]
                 + (b_m[i] - m_m[i] * scm);
    }
    if (i < 3328) {
        int q = i / 832;
        int rem = i - q * 832;
        int r = rem / 52;
        int kk = rem - r * 52;
        g_wspTF[i] = (kk < 49) ? w_span[(q * 49 + kk) * 16 + r] : 0.0f;
    }
    if (i < 208) {
        int q = i / 52, kk = i - q * 52;
        g_bspsF[i] = (kk < 49) ? b_span[q * 49 + kk] : 0.0f;
    }
}

// Partial involution over kernel taps [KB, KB+NKK).  KB must be mult of 4.
template<int KB, int NKK>
__device__ __forceinline__ void inv_partial(
    const float* __restrict__ wspT, const float* __restrict__ bsps,
    const float* __restrict__ ts, const float4* __restrict__ xs4,
    int p, int q, int py, int px, float* inv)
{
    constexpr int NK4 = (NKK + 3) / 4;
    float kern[NK4 * 4];

    const float4* b4 = (const float4*)bsps + q * 13 + KB / 4;
    #pragma unroll
    for (int j = 0; j < NK4; j++) {
        float4 b = b4[j];
        kern[j * 4 + 0] = b.x; kern[j * 4 + 1] = b.y;
        kern[j * 4 + 2] = b.z; kern[j * 4 + 3] = b.w;
    }

    const float4* t4 = (const float4*)(ts + p * TSTR);
    #pragma unroll
    for (int r4 = 0; r4 < 4; r4++) {
        float4 tv = t4[r4];
        float tvals[4] = {tv.x, tv.y, tv.z, tv.w};
        #pragma unroll
        for (int rj = 0; rj < 4; rj++) {
            int r = r4 * 4 + rj;
            const float4* w4 = (const float4*)(wspT + (q * 16 + r) * 52) + KB / 4;
            float t_ = tvals[rj];
            #pragma unroll
            for (int j = 0; j < NK4; j++) {
                float4 w = w4[j];
                kern[j * 4 + 0] = fmaf(w.x, t_, kern[j * 4 + 0]);
                kern[j * 4 + 1] = fmaf(w.y, t_, kern[j * 4 + 1]);
                kern[j * 4 + 2] = fmaf(w.z, t_, kern[j * 4 + 2]);
                kern[j * 4 + 3] = fmaf(w.w, t_, kern[j * 4 + 3]);
            }
        }
    }

    #pragma unroll
    for (int j = 0; j < NKK; j++) {
        int kk = KB + j;
        int ki = kk / 7, kj = kk % 7;
        float kv = kern[j];
        const float4* xp = xs4 + ((py + ki) * HALO + (px + kj)) * (PSTR / 4) + q * 4;
        float4 v0 = xp[0], v1 = xp[1], v2 = xp[2], v3 = xp[3];
        inv[0]  = fmaf(kv, v0.x, inv[0]);
        inv[1]  = fmaf(kv, v0.y, inv[1]);
        inv[2]  = fmaf(kv, v0.z, inv[2]);
        inv[3]  = fmaf(kv, v0.w, inv[3]);
        inv[4]  = fmaf(kv, v1.x, inv[4]);
        inv[5]  = fmaf(kv, v1.y, inv[5]);
        inv[6]  = fmaf(kv, v1.z, inv[6]);
        inv[7]  = fmaf(kv, v1.w, inv[7]);
        inv[8]  = fmaf(kv, v2.x, inv[8]);
        inv[9]  = fmaf(kv, v2.y, inv[9]);
        inv[10] = fmaf(kv, v2.z, inv[10]);
        inv[11] = fmaf(kv, v2.w, inv[11]);
        inv[12] = fmaf(kv, v3.x, inv[12]);
        inv[13] = fmaf(kv, v3.y, inv[13]);
        inv[14] = fmaf(kv, v3.z, inv[14]);
        inv[15] = fmaf(kv, v3.w, inv[15]);
    }
}

__global__ __launch_bounds__(256, 2)
void fused_bottleneck(
    const float* __restrict__ x,
    const float* __restrict__ w_reduce,
    const float* __restrict__ g_r, const float* __restrict__ b_r,
    const float* __restrict__ m_r, const float* __restrict__ v_r,
    const float* __restrict__ g_i, const float* __restrict__ b_i,
    const float* __restrict__ m_i, const float* __restrict__ v_i,
    float* __restrict__ out)
{
    extern __shared__ float sm[];
    float* xs   = sm + OFF_XS;    // [196][68] halo tile
    float* ts   = sm + OFF_TS;    // [64][20]  reduced features
    float* x1s  = sm + OFF_X1S;   // [64][68]  gelu(bn(inv))
    float* wrs  = sm + OFF_WRS;   // [16][64]
    float* wspT = sm + OFF_WSPT;  // [4][16][52]
    float* bsps = sm + OFF_BSPS;  // [4][52]
    float* bvs  = sm + OFF_BVS;   // [128]
    float* wbuf = sm + OFF_WBUF;  // [2][32][68] rotating conv/map weights

    const int tid = threadIdx.x;
    const int gx0 = blockIdx.x * TS;
    const int gy0 = blockIdx.y * TS;
    const int bb  = blockIdx.z;
    const float* xb = x + (size_t)bb * 64 * 96 * 96;

    // ---- Stage halo (zero-padded) ----
    for (int i = tid; i < NHALO * 64; i += 256) {
        int c = i / NHALO;
        int p = i - c * NHALO;
        int hy = p / HALO;
        int hx = p - hy * HALO;
        int gy = gy0 + hy - 3;
        int gx = gx0 + hx - 3;
        float v = 0.0f;
        if ((unsigned)gy < 96u && (unsigned)gx < 96u)
            v = xb[(c * 96 + gy) * 96 + gx];
        xs[p * PSTR + c] = v;
    }
    // ---- Stage small weights (pre-folded/pre-transposed in gmem) ----
    for (int i = tid; i < 1024; i += 256) wrs[i] = w_reduce[i];
    for (int i = tid; i < 3328; i += 256) wspT[i] = g_wspTF[i];
    if (tid < 208) bsps[tid] = g_bspsF[tid];
    if (tid < 128) bvs[tid] = g_bvF[tid];
    __syncthreads();

    const int p  = tid & 63;           // pixel in 8x8 tile
    const int py = p >> 3, px = p & 7;
    const int q  = tid >> 6;           // involution group (warp-uniform)
    const int cpix = (py + 3) * HALO + (px + 3);
    const float4* xs4 = (const float4*)xs;

    // ---- Phase 1: t = relu(bn(w_reduce @ x_center)), 4 rows per thread ----
    {
        const int rr = q;              // rows rr*4 .. rr*4+3
        float a0 = 0.f, a1 = 0.f, a2 = 0.f, a3 = 0.f;
        const float4* xc4 = xs4 + cpix * (PSTR / 4);
        const float4* wr4 = (const float4*)wrs;
        #pragma unroll
        for (int c4 = 0; c4 < 16; c4++) {
            float4 xv = xc4[c4];
            a0 = dot4acc(wr4[(rr * 4 + 0) * 16 + c4], xv, a0);
            a1 = dot4acc(wr4[(rr * 4 + 1) * 16 + c4], xv, a1);
            a2 = dot4acc(wr4[(rr * 4 + 2) * 16 + c4], xv, a2);
            a3 = dot4acc(wr4[(rr * 4 + 3) * 16 + c4], xv, a3);
        }
        float accv[4] = {a0, a1, a2, a3};
        #pragma unroll
        for (int j = 0; j < 4; j++) {
            int r = rr * 4 + j;
            float s = g_r[r] * rsqrtf(v_r[r] + EPS);
            float tv = fmaf(accv[j], s, b_r[r] - m_r[r] * s);
            ts[p * TSTR + r] = fmaxf(tv, 0.0f);
        }
    }
    __syncthreads();

    // ---- Phases 2+3: full involution, kern built in 2 register chunks ----
    float inv[16];
    #pragma unroll
    for (int j = 0; j < 16; j++) inv[j] = 0.0f;
    inv_partial<0, 24>(wspT, bsps, ts, xs4, p, q, py, px, inv);
    inv_partial<24, 25>(wspT, bsps, ts, xs4, p, q, py, px, inv);

    // ---- Phase 4: x1 = gelu(bn_i(inv)) straight from registers ----
    {
        float4* dst = (float4*)(x1s + p * PSTR + q * 16);
        #pragma unroll
        for (int j4 = 0; j4 < 4; j4++) {
            float vv[4];
            #pragma unroll
            for (int k = 0; k < 4; k++) {
                int c = q * 16 + j4 * 4 + k;
                float s = g_i[c] * rsqrtf(v_i[c] + EPS);
                float v = fmaf(inv[j4 * 4 + k], s, b_i[c] - m_i[c] * s);
                vv[k] = gelu_exact(v);
            }
            dst[j4] = make_float4(vv[0], vv[1], vv[2], vv[3]);
        }
    }

    // ---- Phase 5: out = gelu(wc@x1 + wm@x + bias), 4 output chunks of 32 ----
    const int og = tid >> 5;   // warp id 0..7 (uniform) -> 4 outputs per chunk
    const int pg = tid & 31;   // pixels {pg, pg+32}
    int x1o[2], xco[2];
    #pragma unroll
    for (int i = 0; i < 2; i++) {
        int pix = pg + 32 * i;
        int py2 = pix >> 3, px2 = pix & 7;
        x1o[i] = pix * (PSTR / 4);
        xco[i] = ((py2 + 3) * HALO + (px2 + 3)) * (PSTR / 4);
    }
    const float4* x14 = (const float4*)x1s;
    float* ob = out + (size_t)bb * 128 * 96 * 96;
    const int row0 = gy0 + (pg >> 3);
    const int colp = gx0 + (pg & 7);

    for (int ch = 0; ch < 4; ch++) {
        __syncthreads();   // protects x1s write (ch=0) / previous wbuf reads
        // stage 32 outputs of folded conv+map weights into wbuf
        {
            const float4* gc4 = (const float4*)(g_wcF + ch * 32 * 64);
            const float4* gm4 = (const float4*)(g_wmF + ch * 32 * 64);
            for (int i = tid; i < 512; i += 256) {
                int o = i >> 4, c4 = i & 15;
                ((float4*)(wbuf + o * PSTR))[c4] = gc4[i];
                ((float4*)(wbuf + 32 * PSTR + o * PSTR))[c4] = gm4[i];
            }
        }
        __syncthreads();

        const int o0 = ch * 32 + og * 4;
        float acc[4][2];
        #pragma unroll
        for (int j = 0; j < 4; j++) {
            float bv = bvs[o0 + j];
            acc[j][0] = bv;
            acc[j][1] = bv;
        }
        const float4* wc4 = (const float4*)(wbuf + (og * 4) * PSTR);
        const float4* wm4 = (const float4*)(wbuf + 32 * PSTR + (og * 4) * PSTR);
        #pragma unroll 4
        for (int c4 = 0; c4 < 16; c4++) {
            float4 xv1a = x14[x1o[0] + c4];
            float4 xv1b = x14[x1o[1] + c4];
            float4 xv0a = xs4[xco[0] + c4];
            float4 xv0b = xs4[xco[1] + c4];
            #pragma unroll
            for (int j = 0; j < 4; j++) {
                float4 wc = wc4[j * (PSTR / 4) + c4];
                float4 wm = wm4[j * (PSTR / 4) + c4];
                acc[j][0] = dot4acc(wc, xv1a, acc[j][0]);
                acc[j][0] = dot4acc(wm, xv0a, acc[j][0]);
                acc[j][1] = dot4acc(wc, xv1b, acc[j][1]);
                acc[j][1] = dot4acc(wm, xv0b, acc[j][1]);
            }
        }
        #pragma unroll
        for (int j = 0; j < 4; j++) {
            int o = o0 + j;
            ob[(o * 96 + row0)     * 96 + colp] = gelu_exact(acc[j][0]);
            ob[(o * 96 + row0 + 4) * 96 + colp] = gelu_exact(acc[j][1]);
        }
    }
}

extern "C" void kernel_launch(void* const* d_in, const int* in_sizes, int n_in,
                              void* d_out, int out_size) {
    const float* x        = (const float*)d_in[0];
    const float* w_reduce = (const float*)d_in[1];
    const float* g_r      = (const float*)d_in[2];
    const float* b_r      = (const float*)d_in[3];
    const float* m_r      = (const float*)d_in[4];
    const float* v_r      = (const float*)d_in[5];
    const float* w_span   = (const float*)d_in[6];
    const float* b_span   = (const float*)d_in[7];
    const float* g_i      = (const float*)d_in[8];
    const float* b_i      = (const float*)d_in[9];
    const float* m_i      = (const float*)d_in[10];
    const float* v_i      = (const float*)d_in[11];
    const float* w_conv   = (const float*)d_in[12];
    const float* g_c      = (const float*)d_in[13];
    const float* b_c      = (const float*)d_in[14];
    const float* m_c      = (const float*)d_in[15];
    const float* v_c      = (const float*)d_in[16];
    const float* w_map    = (const float*)d_in[17];
    const float* b_map    = (const float*)d_in[18];
    const float* g_m      = (const float*)d_in[19];
    const float* b_m      = (const float*)d_in[20];
    const float* m_m      = (const float*)d_in[21];
    const float* v_m      = (const float*)d_in[22];

    fold_weights<<<32, 256>>>(w_span, b_span, w_conv,
                              g_c, b_c, m_c, v_c,
                              w_map, b_map, g_m, b_m, m_m, v_m);

    cudaFuncSetAttribute(fused_bottleneck,
                         cudaFuncAttributeMaxDynamicSharedMemorySize, SMEM_BYTES);

    dim3 grid(96 / TS, 96 / TS, 4);
    dim3 block(256);
    fused_bottleneck<<<grid, block, SMEM_BYTES>>>(
        x, w_reduce, g_r, b_r, m_r, v_r,
        g_i, b_i, m_i, v_i, (float*)d_out);
}

// round 15
// speedup vs baseline: 1.2073x; 1.1044x over previous
#include <cuda_runtime.h>
#include <math.h>

#define EPS 1e-5f
#define TS 8
#define HALO 14          // TS + 6
#define PSTR 68          // per-pixel channel stride in floats (64 + 4 pad)
#define NHALO 196        // 14*14
#define TSTR 20          // ts row stride

// smem layout (floats) — 26512 floats = 106,048 B (2 CTAs/SM)
// Union region: phase-1/2 scratch (wrs/wspT/bsps/ts, dead after phase 3)
// is overlaid by the phase-5 weight buffer (64 outputs x 2 tensors).
#define OFF_XS   0
#define OFF_X1S  (OFF_XS  + NHALO * PSTR)   // +13328
#define OFF_BVS  (OFF_X1S + 64 * PSTR)      // +4352
#define OFF_U    (OFF_BVS + 128)
#define OFF_WRS  OFF_U                      // [16][64]   1024
#define OFF_WSPT (OFF_WRS  + 1024)          // [4][16][52] 3328
#define OFF_BSPS (OFF_WSPT + 3328)          // [4][52]    208
#define OFF_TS   (OFF_BSPS + 208)           // [64][20]   1280
#define OFF_WBUF OFF_U                      // [2][64][68] 8704 (overlay)
#define SMEM_FLOATS (OFF_U + 2 * 64 * PSTR)
#define SMEM_BYTES (SMEM_FLOATS * 4)

// Pre-folded weights (written by fold_weights kernel each launch)
__device__ float g_wcF[8192];    // w_conv * bn_c scale, [o][c]
__device__ float g_wmF[8192];    // w_map  * bn_m scale, [o][c]
__device__ float g_bvF[128];     // fused bias
__device__ float g_wspTF[3328];  // span weights transposed [q][r][52]
__device__ float g_bspsF[208];   // span bias padded [q][52]

__device__ __forceinline__ float dot4acc(float4 w, float4 v, float a) {
    a = fmaf(w.x, v.x, a);
    a = fmaf(w.y, v.y, a);
    a = fmaf(w.z, v.z, a);
    a = fmaf(w.w, v.w, a);
    return a;
}

__device__ __forceinline__ float gelu_exact(float v) {
    return 0.5f * v * (1.0f + erff(v * 0.70710678118654752f));
}

__global__ void fold_weights(
    const float* __restrict__ w_span, const float* __restrict__ b_span,
    const float* __restrict__ w_conv,
    const float* __restrict__ g_c, const float* __restrict__ b_c,
    const float* __restrict__ m_c, const float* __restrict__ v_c,
    const float* __restrict__ w_map, const float* __restrict__ b_map,
    const float* __restrict__ g_m, const float* __restrict__ b_m,
    const float* __restrict__ m_m, const float* __restrict__ v_m)
{
    int i = blockIdx.x * 256 + threadIdx.x;
    if (i < 8192) {
        int o = i >> 6;
        float scc = g_c[o] * rsqrtf(v_c[o] + EPS);
        float scm = g_m[o] * rsqrtf(v_m[o] + EPS);
        g_wcF[i] = w_conv[i] * scc;
        g_wmF[i] = w_map[i]  * scm;
    }
    if (i < 128) {
        float scc = g_c[i] * rsqrtf(v_c[i] + EPS);
        float scm = g_m[i] * rsqrtf(v_m[i] + EPS);
        g_bvF[i] = (b_c[i] - m_c[i] * scc)
                 + scm * b_map[i]
                 + (b_m[i] - m_m[i] * scm);
    }
    if (i < 3328) {
        int q = i / 832;
        int rem = i - q * 832;
        int r = rem / 52;
        int kk = rem - r * 52;
        g_wspTF[i] = (kk < 49) ? w_span[(q * 49 + kk) * 16 + r] : 0.0f;
    }
    if (i < 208) {
        int q = i / 52, kk = i - q * 52;
        g_bspsF[i] = (kk < 49) ? b_span[q * 49 + kk] : 0.0f;
    }
}

// Partial involution over kernel taps [KB, KB+NKK).  KB must be mult of 4.
template<int KB, int NKK>
__device__ __forceinline__ void inv_partial(
    const float* __restrict__ wspT, const float* __restrict__ bsps,
    const float* __restrict__ ts, const float4* __restrict__ xs4,
    int p, int q, int py, int px, float* inv)
{
    constexpr int NK4 = (NKK + 3) / 4;
    float kern[NK4 * 4];

    const float4* b4 = (const float4*)bsps + q * 13 + KB / 4;
    #pragma unroll
    for (int j = 0; j < NK4; j++) {
        float4 b = b4[j];
        kern[j * 4 + 0] = b.x; kern[j * 4 + 1] = b.y;
        kern[j * 4 + 2] = b.z; kern[j * 4 + 3] = b.w;
    }

    const float4* t4 = (const float4*)(ts + p * TSTR);
    #pragma unroll
    for (int r4 = 0; r4 < 4; r4++) {
        float4 tv = t4[r4];
        float tvals[4] = {tv.x, tv.y, tv.z, tv.w};
        #pragma unroll
        for (int rj = 0; rj < 4; rj++) {
            int r = r4 * 4 + rj;
            const float4* w4 = (const float4*)(wspT + (q * 16 + r) * 52) + KB / 4;
            float t_ = tvals[rj];
            #pragma unroll
            for (int j = 0; j < NK4; j++) {
                float4 w = w4[j];
                kern[j * 4 + 0] = fmaf(w.x, t_, kern[j * 4 + 0]);
                kern[j * 4 + 1] = fmaf(w.y, t_, kern[j * 4 + 1]);
                kern[j * 4 + 2] = fmaf(w.z, t_, kern[j * 4 + 2]);
                kern[j * 4 + 3] = fmaf(w.w, t_, kern[j * 4 + 3]);
            }
        }
    }

    #pragma unroll
    for (int j = 0; j < NKK; j++) {
        int kk = KB + j;
        int ki = kk / 7, kj = kk % 7;
        float kv = kern[j];
        const float4* xp = xs4 + ((py + ki) * HALO + (px + kj)) * (PSTR / 4) + q * 4;
        float4 v0 = xp[0], v1 = xp[1], v2 = xp[2], v3 = xp[3];
        inv[0]  = fmaf(kv, v0.x, inv[0]);
        inv[1]  = fmaf(kv, v0.y, inv[1]);
        inv[2]  = fmaf(kv, v0.z, inv[2]);
        inv[3]  = fmaf(kv, v0.w, inv[3]);
        inv[4]  = fmaf(kv, v1.x, inv[4]);
        inv[5]  = fmaf(kv, v1.y, inv[5]);
        inv[6]  = fmaf(kv, v1.z, inv[6]);
        inv[7]  = fmaf(kv, v1.w, inv[7]);
        inv[8]  = fmaf(kv, v2.x, inv[8]);
        inv[9]  = fmaf(kv, v2.y, inv[9]);
        inv[10] = fmaf(kv, v2.z, inv[10]);
        inv[11] = fmaf(kv, v2.w, inv[11]);
        inv[12] = fmaf(kv, v3.x, inv[12]);
        inv[13] = fmaf(kv, v3.y, inv[13]);
        inv[14] = fmaf(kv, v3.z, inv[14]);
        inv[15] = fmaf(kv, v3.w, inv[15]);
    }
}

__global__ __launch_bounds__(256, 2)
void fused_bottleneck(
    const float* __restrict__ x,
    const float* __restrict__ w_reduce,
    const float* __restrict__ g_r, const float* __restrict__ b_r,
    const float* __restrict__ m_r, const float* __restrict__ v_r,
    const float* __restrict__ g_i, const float* __restrict__ b_i,
    const float* __restrict__ m_i, const float* __restrict__ v_i,
    float* __restrict__ out)
{
    extern __shared__ float sm[];
    float* xs   = sm + OFF_XS;    // [196][68] halo tile
    float* x1s  = sm + OFF_X1S;   // [64][68]  gelu(bn(inv))
    float* bvs  = sm + OFF_BVS;   // [128]
    float* wrs  = sm + OFF_WRS;   // [16][64]        (phase 1, dead after)
    float* wspT = sm + OFF_WSPT;  // [4][16][52]     (phase 2, dead after)
    float* bsps = sm + OFF_BSPS;  // [4][52]         (phase 2, dead after)
    float* ts   = sm + OFF_TS;    // [64][20]        (phase 2, dead after)
    float* wbuf = sm + OFF_WBUF;  // [2][64][68] overlay (phase 5)

    const int tid = threadIdx.x;
    const int gx0 = blockIdx.x * TS;
    const int gy0 = blockIdx.y * TS;
    const int bb  = blockIdx.z;
    const float* xb = x + (size_t)bb * 64 * 96 * 96;

    // ---- Stage halo (zero-padded) ----
    for (int i = tid; i < NHALO * 64; i += 256) {
        int c = i / NHALO;
        int p = i - c * NHALO;
        int hy = p / HALO;
        int hx = p - hy * HALO;
        int gy = gy0 + hy - 3;
        int gx = gx0 + hx - 3;
        float v = 0.0f;
        if ((unsigned)gy < 96u && (unsigned)gx < 96u)
            v = xb[(c * 96 + gy) * 96 + gx];
        xs[p * PSTR + c] = v;
    }
    // ---- Stage small weights (pre-folded/pre-transposed in gmem) ----
    for (int i = tid; i < 1024; i += 256) wrs[i] = w_reduce[i];
    for (int i = tid; i < 3328; i += 256) wspT[i] = g_wspTF[i];
    if (tid < 208) bsps[tid] = g_bspsF[tid];
    if (tid < 128) bvs[tid] = g_bvF[tid];
    __syncthreads();

    const int p  = tid & 63;           // pixel in 8x8 tile
    const int py = p >> 3, px = p & 7;
    const int q  = tid >> 6;           // involution group (warp-uniform)
    const int cpix = (py + 3) * HALO + (px + 3);
    const float4* xs4 = (const float4*)xs;

    // ---- Phase 1: t = relu(bn(w_reduce @ x_center)), 4 rows per thread ----
    {
        const int rr = q;              // rows rr*4 .. rr*4+3
        float a0 = 0.f, a1 = 0.f, a2 = 0.f, a3 = 0.f;
        const float4* xc4 = xs4 + cpix * (PSTR / 4);
        const float4* wr4 = (const float4*)wrs;
        #pragma unroll
        for (int c4 = 0; c4 < 16; c4++) {
            float4 xv = xc4[c4];
            a0 = dot4acc(wr4[(rr * 4 + 0) * 16 + c4], xv, a0);
            a1 = dot4acc(wr4[(rr * 4 + 1) * 16 + c4], xv, a1);
            a2 = dot4acc(wr4[(rr * 4 + 2) * 16 + c4], xv, a2);
            a3 = dot4acc(wr4[(rr * 4 + 3) * 16 + c4], xv, a3);
        }
        float accv[4] = {a0, a1, a2, a3};
        #pragma unroll
        for (int j = 0; j < 4; j++) {
            int r = rr * 4 + j;
            float s = g_r[r] * rsqrtf(v_r[r] + EPS);
            float tv = fmaf(accv[j], s, b_r[r] - m_r[r] * s);
            ts[p * TSTR + r] = fmaxf(tv, 0.0f);
        }
    }
    __syncthreads();

    // ---- Phases 2+3: full involution, kern built in 2 register chunks ----
    float inv[16];
    #pragma unroll
    for (int j = 0; j < 16; j++) inv[j] = 0.0f;
    inv_partial<0, 24>(wspT, bsps, ts, xs4, p, q, py, px, inv);
    inv_partial<24, 25>(wspT, bsps, ts, xs4, p, q, py, px, inv);

    // ---- Phase 4: x1 = gelu(bn_i(inv)) straight from registers ----
    {
        float4* dst = (float4*)(x1s + p * PSTR + q * 16);
        #pragma unroll
        for (int j4 = 0; j4 < 4; j4++) {
            float vv[4];
            #pragma unroll
            for (int k = 0; k < 4; k++) {
                int c = q * 16 + j4 * 4 + k;
                float s = g_i[c] * rsqrtf(v_i[c] + EPS);
                float v = fmaf(inv[j4 * 4 + k], s, b_i[c] - m_i[c] * s);
                vv[k] = gelu_exact(v);
            }
            dst[j4] = make_float4(vv[0], vv[1], vv[2], vv[3]);
        }
    }

    // ---- Phase 5: out = gelu(wc@x1 + wm@x + bias), 2 chunks of 64 outputs ----
    // Per thread: 8 outputs x 2 strided pixels. og warp-uniform -> all weight
    // loads broadcast (1 wf). Input lane stride = 1 pixel (68 words): no
    // conflicts. Inputs re-read only 2x (chunks) instead of 4x.
    const int og = tid >> 5;   // warp id 0..7 -> outputs og*8..og*8+7 per chunk
    const int pg = tid & 31;   // pixels {pg, pg+32}
    int x1o[2], xco[2];
    #pragma unroll
    for (int i = 0; i < 2; i++) {
        int pix = pg + 32 * i;
        int py2 = pix >> 3, px2 = pix & 7;
        x1o[i] = pix * (PSTR / 4);
        xco[i] = ((py2 + 3) * HALO + (px2 + 3)) * (PSTR / 4);
    }
    const float4* x14 = (const float4*)x1s;
    float* ob = out + (size_t)bb * 128 * 96 * 96;
    const int row0 = gy0 + (pg >> 3);
    const int colp = gx0 + (pg & 7);

    for (int ch = 0; ch < 2; ch++) {
        __syncthreads();   // x1s ready (ch=0) / prior wbuf reads done (ch=1);
                           // also retires phase-1/2 scratch before overlay
        // stage 64 outputs of folded conv+map weights into wbuf
        {
            const float4* gc4 = (const float4*)(g_wcF + ch * 64 * 64);
            const float4* gm4 = (const float4*)(g_wmF + ch * 64 * 64);
            for (int i = tid; i < 1024; i += 256) {
                int o = i >> 4, c4 = i & 15;
                ((float4*)(wbuf + o * PSTR))[c4] = gc4[i];
                ((float4*)(wbuf + 64 * PSTR + o * PSTR))[c4] = gm4[i];
            }
        }
        __syncthreads();

        const int o0 = ch * 64 + og * 8;
        float acc[8][2];
        #pragma unroll
        for (int j = 0; j < 8; j++) {
            float bv = bvs[o0 + j];
            acc[j][0] = bv;
            acc[j][1] = bv;
        }
        const float4* wc4 = (const float4*)(wbuf + (og * 8) * PSTR);
        const float4* wm4 = (const float4*)(wbuf + 64 * PSTR + (og * 8) * PSTR);
        #pragma unroll 2
        for (int c4 = 0; c4 < 16; c4++) {
            float4 xv1a = x14[x1o[0] + c4];
            float4 xv1b = x14[x1o[1] + c4];
            float4 xv0a = xs4[xco[0] + c4];
            float4 xv0b = xs4[xco[1] + c4];
            #pragma unroll
            for (int j = 0; j < 8; j++) {
                float4 wc = wc4[j * (PSTR / 4) + c4];
                float4 wm = wm4[j * (PSTR / 4) + c4];
                acc[j][0] = dot4acc(wc, xv1a, acc[j][0]);
                acc[j][0] = dot4acc(wm, xv0a, acc[j][0]);
                acc[j][1] = dot4acc(wc, xv1b, acc[j][1]);
                acc[j][1] = dot4acc(wm, xv0b, acc[j][1]);
            }
        }
        #pragma unroll
        for (int j = 0; j < 8; j++) {
            int o = o0 + j;
            ob[(o * 96 + row0)     * 96 + colp] = gelu_exact(acc[j][0]);
            ob[(o * 96 + row0 + 4) * 96 + colp] = gelu_exact(acc[j][1]);
        }
    }
}

extern "C" void kernel_launch(void* const* d_in, const int* in_sizes, int n_in,
                              void* d_out, int out_size) {
    const float* x        = (const float*)d_in[0];
    const float* w_reduce = (const float*)d_in[1];
    const float* g_r      = (const float*)d_in[2];
    const float* b_r      = (const float*)d_in[3];
    const float* m_r      = (const float*)d_in[4];
    const float* v_r      = (const float*)d_in[5];
    const float* w_span   = (const float*)d_in[6];
    const float* b_span   = (const float*)d_in[7];
    const float* g_i      = (const float*)d_in[8];
    const float* b_i      = (const float*)d_in[9];
    const float* m_i      = (const float*)d_in[10];
    const float* v_i      = (const float*)d_in[11];
    const float* w_conv   = (const float*)d_in[12];
    const float* g_c      = (const float*)d_in[13];
    const float* b_c      = (const float*)d_in[14];
    const float* m_c      = (const float*)d_in[15];
    const float* v_c      = (const float*)d_in[16];
    const float* w_map    = (const float*)d_in[17];
    const float* b_map    = (const float*)d_in[18];
    const float* g_m      = (const float*)d_in[19];
    const float* b_m      = (const float*)d_in[20];
    const float* m_m      = (const float*)d_in[21];
    const float* v_m      = (const float*)d_in[22];

    fold_weights<<<32, 256>>>(w_span, b_span, w_conv,
                              g_c, b_c, m_c, v_c,
                              w_map, b_map, g_m, b_m, m_m, v_m);

    cudaFuncSetAttribute(fused_bottleneck,
                         cudaFuncAttributeMaxDynamicSharedMemorySize, SMEM_BYTES);

    dim3 grid(96 / TS, 96 / TS, 4);
    dim3 block(256);
    fused_bottleneck<<<grid, block, SMEM_BYTES>>>(
        x, w_reduce, g_r, b_r, m_r, v_r,
        g_i, b_i, m_i, v_i, (float*)d_out);
}